// round 4
// baseline (speedup 1.0000x reference)
#include <cuda_runtime.h>
#include <cuda_bf16.h>
#include <math.h>

#define Nn 100000
#define Ee 1600000
#define Gg 512
#define Hh 128

// ---------------- scratch (device globals; no allocation allowed) ----------
__device__ float g_h0[(size_t)Nn * Hh];
__device__ float g_h1[(size_t)Nn * Hh];
__device__ float g_agg[(size_t)Nn * Hh];
__device__ float g_deg_out[Nn];
__device__ float g_deg_in[Nn];
__device__ float g_norm_out[Nn];
__device__ float g_norm_in[Nn];
__device__ float g_gsum[(size_t)Gg * Hh];

// ---------------- zero kernels ---------------------------------------------
__global__ void zero_agg_kernel() {
    size_t i = (size_t)blockIdx.x * blockDim.x + threadIdx.x;
    float4* p = (float4*)g_agg;
    size_t n4 = (size_t)Nn * Hh / 4;
    if (i < n4) p[i] = make_float4(0.f, 0.f, 0.f, 0.f);
}

__global__ void zero_deg_kernel() {
    int i = blockIdx.x * blockDim.x + threadIdx.x;
    if (i < Nn) { g_deg_out[i] = 0.f; g_deg_in[i] = 0.f; }
}

__global__ void zero_g_kernel() {
    int i = blockIdx.x * blockDim.x + threadIdx.x;
    if (i < Gg * Hh) g_gsum[i] = 0.f;
}

// ---------------- degrees + norms ------------------------------------------
__global__ void degree_kernel(const int* __restrict__ src, const int* __restrict__ dst) {
    int e = blockIdx.x * blockDim.x + threadIdx.x;
    if (e < Ee) {
        atomicAdd(&g_deg_out[src[e]], 1.f);
        atomicAdd(&g_deg_in[dst[e]], 1.f);
    }
}

__global__ void norm_kernel() {
    int i = blockIdx.x * blockDim.x + threadIdx.x;
    if (i < Nn) {
        g_norm_out[i] = rsqrtf(fmaxf(g_deg_out[i], 1.f));
        g_norm_in[i]  = rsqrtf(fmaxf(g_deg_in[i], 1.f));
    }
}

// ---------------- edge scatter: agg[dst] += h[src] * norm_out[src] ---------
// one warp per edge; each lane handles one float4 (32*4 = 128 feats)
__global__ void scatter_kernel(const float* __restrict__ h,
                               const int* __restrict__ src,
                               const int* __restrict__ dst) {
    int warp = (blockIdx.x * blockDim.x + threadIdx.x) >> 5;
    int lane = threadIdx.x & 31;
    if (warp >= Ee) return;
    int s = src[warp];
    int d = dst[warp];
    float ns = g_norm_out[s];
    float4 v = *((const float4*)(h + (size_t)s * Hh) + lane);
    v.x *= ns; v.y *= ns; v.z *= ns; v.w *= ns;
    atomicAdd((float4*)(g_agg + (size_t)d * Hh) + lane, v);
}

// ---------------- fused GEMM: out = relu((agg*norm_in) @ W + b) ------------
// M-tile 128, N = K = 128 fixed. 256 threads, each an 8x8 microtile.
__global__ void gemm_bias_relu_kernel(const float* __restrict__ A,
                                      const float* __restrict__ W,
                                      const float* __restrict__ b,
                                      float* __restrict__ out, int M) {
    __shared__ float As[128][33];
    __shared__ float Ws[32][132];

    int tid = threadIdx.x;       // 0..255
    int tx = tid & 15;           // col group
    int ty = tid >> 4;           // row group
    int row0 = blockIdx.x * 128;

    float acc[8][8];
#pragma unroll
    for (int i = 0; i < 8; i++)
#pragma unroll
        for (int j = 0; j < 8; j++) acc[i][j] = 0.f;

    for (int kc = 0; kc < 128; kc += 32) {
        // load A chunk (128 rows x 32 cols), scaled by norm_in[row]
#pragma unroll
        for (int p = 0; p < 4; ++p) {
            int r = (tid >> 3) + p * 32;
            int c = (tid & 7) * 4;
            int gr = row0 + r;
            float4 v = make_float4(0.f, 0.f, 0.f, 0.f);
            float s = 0.f;
            if (gr < M) {
                v = *(const float4*)(A + (size_t)gr * 128 + kc + c);
                s = g_norm_in[gr];
            }
            As[r][c + 0] = v.x * s;
            As[r][c + 1] = v.y * s;
            As[r][c + 2] = v.z * s;
            As[r][c + 3] = v.w * s;
        }
        // load W chunk (32 rows x 128 cols)
#pragma unroll
        for (int p = 0; p < 4; ++p) {
            int idx = tid + p * 256;      // float4 units, 1024 total
            int r = idx >> 5;             // 32 float4 per row
            int c = (idx & 31) * 4;
            float4 v = *(const float4*)(W + (size_t)(kc + r) * 128 + c);
            Ws[r][c + 0] = v.x;
            Ws[r][c + 1] = v.y;
            Ws[r][c + 2] = v.z;
            Ws[r][c + 3] = v.w;
        }
        __syncthreads();

#pragma unroll
        for (int k = 0; k < 32; ++k) {
            float a[8], w[8];
#pragma unroll
            for (int i = 0; i < 8; i++) a[i] = As[ty * 8 + i][k];
#pragma unroll
            for (int j = 0; j < 8; j++) w[j] = Ws[k][tx * 8 + j];
#pragma unroll
            for (int i = 0; i < 8; i++)
#pragma unroll
                for (int j = 0; j < 8; j++) acc[i][j] += a[i] * w[j];
        }
        __syncthreads();
    }

    // epilogue: bias + relu
#pragma unroll
    for (int i = 0; i < 8; i++) {
        int gr = row0 + ty * 8 + i;
        if (gr >= M) break;
#pragma unroll
        for (int j = 0; j < 8; j++) {
            int c = tx * 8 + j;
            float v = acc[i][j] + b[c];
            out[(size_t)gr * 128 + c] = fmaxf(v, 0.f);
        }
    }
}

// ---------------- readout: g[node2graph[n]] += h[n] ------------------------
__global__ void readout_kernel(const float* __restrict__ h,
                               const int* __restrict__ n2g) {
    int warp = (blockIdx.x * blockDim.x + threadIdx.x) >> 5;
    int lane = threadIdx.x & 31;
    if (warp >= Nn) return;
    int g = n2g[warp];
    float4 v = *((const float4*)(h + (size_t)warp * Hh) + lane);
    atomicAdd((float4*)(g_gsum + (size_t)g * Hh) + lane, v);
}

// ---------------- MLP head: relu(g@Wm1+bm1) @ Wm2 + bm2 --------------------
__global__ void mlp_kernel(const float* __restrict__ Wm1, const float* __restrict__ bm1,
                           const float* __restrict__ Wm2, const float* __restrict__ bm2,
                           float* __restrict__ out) {
    int gid = blockIdx.x;        // 0..G-1
    int j = threadIdx.x;         // 0..127
    const float* grow = g_gsum + (size_t)gid * Hh;
    float acc = bm1[j];
#pragma unroll 8
    for (int k = 0; k < Hh; k++) acc += grow[k] * Wm1[(size_t)k * Hh + j];
    acc = fmaxf(acc, 0.f);

    __shared__ float sm[Hh];
    sm[j] = acc * Wm2[j];        // Wm2 is [H,1]
    __syncthreads();
    for (int s = 64; s > 0; s >>= 1) {
        if (j < s) sm[j] += sm[j + s];
        __syncthreads();
    }
    if (j == 0) out[gid] = sm[0] + bm2[0];
}

// ---------------- launch ----------------------------------------------------
extern "C" void kernel_launch(void* const* d_in, const int* in_sizes, int n_in,
                              void* d_out, int out_size) {
    const float* x   = (const float*)d_in[0];
    const int* src   = (const int*)d_in[1];
    const int* dst   = (const int*)d_in[2];
    const int* n2g   = (const int*)d_in[3];
    const float* W0  = (const float*)d_in[4];
    const float* b0  = (const float*)d_in[5];
    const float* W1  = (const float*)d_in[6];
    const float* b1  = (const float*)d_in[7];
    const float* W2  = (const float*)d_in[8];
    const float* b2  = (const float*)d_in[9];
    const float* Wm1 = (const float*)d_in[10];
    const float* bm1 = (const float*)d_in[11];
    const float* Wm2 = (const float*)d_in[12];
    const float* bm2 = (const float*)d_in[13];
    float* out = (float*)d_out;

    void *p_h0, *p_h1, *p_agg;
    cudaGetSymbolAddress(&p_h0, g_h0);
    cudaGetSymbolAddress(&p_h1, g_h1);
    cudaGetSymbolAddress(&p_agg, g_agg);
    float* h0  = (float*)p_h0;
    float* h1  = (float*)p_h1;
    float* agg = (float*)p_agg;

    const int ZAGG_BLOCKS = (int)(((size_t)Nn * Hh / 4 + 255) / 256);
    const int SCAT_BLOCKS = (Ee + 7) / 8;          // 8 warps/block (256 thr)
    const int GEMM_BLOCKS = (Nn + 127) / 128;
    const int RD_BLOCKS   = (Nn + 7) / 8;

    // degrees + norms
    zero_deg_kernel<<<(Nn + 255) / 256, 256>>>();
    degree_kernel<<<(Ee + 255) / 256, 256>>>(src, dst);
    norm_kernel<<<(Nn + 255) / 256, 256>>>();

    // layer 1: x -> h0
    zero_agg_kernel<<<ZAGG_BLOCKS, 256>>>();
    scatter_kernel<<<SCAT_BLOCKS, 256>>>(x, src, dst);
    gemm_bias_relu_kernel<<<GEMM_BLOCKS, 256>>>(agg, W0, b0, h0, Nn);

    // layer 2: h0 -> h1
    zero_agg_kernel<<<ZAGG_BLOCKS, 256>>>();
    scatter_kernel<<<SCAT_BLOCKS, 256>>>(h0, src, dst);
    gemm_bias_relu_kernel<<<GEMM_BLOCKS, 256>>>(agg, W1, b1, h1, Nn);

    // layer 3: h1 -> h0
    zero_agg_kernel<<<ZAGG_BLOCKS, 256>>>();
    scatter_kernel<<<SCAT_BLOCKS, 256>>>(h1, src, dst);
    gemm_bias_relu_kernel<<<GEMM_BLOCKS, 256>>>(agg, W2, b2, h0, Nn);

    // readout + MLP head
    zero_g_kernel<<<(Gg * Hh + 255) / 256, 256>>>();
    readout_kernel<<<RD_BLOCKS, 256>>>(h0, n2g);
    mlp_kernel<<<Gg, Hh>>>(Wm1, bm1, Wm2, bm2, out);
}

// round 6
// speedup vs baseline: 2.2196x; 2.2196x over previous
#include <cuda_runtime.h>
#include <cuda_bf16.h>
#include <math.h>

#define Nn 100000
#define Ee 1600000
#define Gg 512
#define Hh 128
#define SCAN_CHUNK 1024
#define NBLK_SCAN ((Nn + SCAN_CHUNK - 1) / SCAN_CHUNK)   // 98

// ---------------- scratch (device globals; no allocation allowed) ----------
__device__ float g_h0[(size_t)Nn * Hh];
__device__ float g_h1[(size_t)Nn * Hh];
__device__ float g_agg[(size_t)Nn * Hh];
__device__ float g_norm_out[Nn];
__device__ float g_norm_in[Nn];
__device__ float g_gsum[(size_t)Gg * Hh];

__device__ int g_cnt_in[Nn];
__device__ int g_cnt_out[Nn];
__device__ int g_rowptr[Nn + 1];
__device__ int g_cursor[Nn];
__device__ int g_csrc[Ee];
__device__ int g_partials[256];

// ---------------- zero kernels ---------------------------------------------
__global__ void zero_cnt_kernel() {
    int i = blockIdx.x * blockDim.x + threadIdx.x;
    if (i < Nn) { g_cnt_in[i] = 0; g_cnt_out[i] = 0; }
}

__global__ void zero_g_kernel() {
    int i = blockIdx.x * blockDim.x + threadIdx.x;
    if (i < Gg * Hh) g_gsum[i] = 0.f;
}

// ---------------- histogram (also yields degrees) --------------------------
__global__ void hist_kernel(const int* __restrict__ src, const int* __restrict__ dst) {
    int e = blockIdx.x * blockDim.x + threadIdx.x;
    if (e < Ee) {
        atomicAdd(&g_cnt_in[dst[e]], 1);
        atomicAdd(&g_cnt_out[src[e]], 1);
    }
}

__global__ void norm_kernel() {
    int i = blockIdx.x * blockDim.x + threadIdx.x;
    if (i < Nn) {
        g_norm_out[i] = rsqrtf(fmaxf((float)g_cnt_out[i], 1.f));
        g_norm_in[i]  = rsqrtf(fmaxf((float)g_cnt_in[i], 1.f));
    }
}

// ---------------- 3-phase exclusive scan of g_cnt_in -> g_rowptr -----------
// phase 1: per-block (1024 elems, 256 thr x 4) local exclusive scan + partial
__global__ void scan1_kernel() {
    __shared__ int sm[256];
    int b = blockIdx.x, t = threadIdx.x;
    int base = b * SCAN_CHUNK + t * 4;
    int v[4]; int s = 0;
#pragma unroll
    for (int i = 0; i < 4; i++) {
        int idx = base + i;
        v[i] = (idx < Nn) ? g_cnt_in[idx] : 0;
        s += v[i];
    }
    sm[t] = s;
    __syncthreads();
    for (int off = 1; off < 256; off <<= 1) {
        int x = (t >= off) ? sm[t - off] : 0;
        __syncthreads();
        if (t >= off) sm[t] += x;
        __syncthreads();
    }
    int run = (t > 0) ? sm[t - 1] : 0;   // exclusive prefix of this thread
#pragma unroll
    for (int i = 0; i < 4; i++) {
        int idx = base + i;
        if (idx < Nn) g_rowptr[idx] = run;
        run += v[i];
    }
    if (t == 255) g_partials[b] = sm[255];
}

// phase 2: single-block scan of the block partials (P = NBLK_SCAN <= 128)
__global__ void scan2_kernel(int P) {
    __shared__ int sm[128];
    int t = threadIdx.x;
    sm[t] = (t < P) ? g_partials[t] : 0;
    __syncthreads();
    for (int off = 1; off < 128; off <<= 1) {
        int x = (t >= off) ? sm[t - off] : 0;
        __syncthreads();
        if (t >= off) sm[t] += x;
        __syncthreads();
    }
    if (t < P) g_partials[t] = (t > 0) ? sm[t - 1] : 0;  // exclusive
    if (t == P - 1) g_rowptr[Nn] = sm[P - 1];            // total = E
}

// phase 3: add block offsets; init cursor
__global__ void scan3_kernel() {
    int i = blockIdx.x * blockDim.x + threadIdx.x;
    if (i < Nn) {
        int v = g_rowptr[i] + g_partials[i / SCAN_CHUNK];
        g_rowptr[i] = v;
        g_cursor[i] = v;
    }
}

// ---------------- permute edges into CSR-by-dst ----------------------------
__global__ void permute_kernel(const int* __restrict__ src, const int* __restrict__ dst) {
    int e = blockIdx.x * blockDim.x + threadIdx.x;
    if (e < Ee) {
        int pos = atomicAdd(&g_cursor[dst[e]], 1);
        g_csrc[pos] = src[e];
    }
}

// ---------------- gather aggregation ---------------------------------------
// agg[n] = norm_in[n] * sum_{e in in(n)} h[src(e)] * norm_out[src(e)]
// one warp per node; lane handles one float4 (32*4 = 128 feats)
__global__ void gather_kernel(const float* __restrict__ h,
                              float* __restrict__ agg) {
    int node = (blockIdx.x * blockDim.x + threadIdx.x) >> 5;
    int lane = threadIdx.x & 31;
    if (node >= Nn) return;
    int e = __ldg(&g_rowptr[node]);
    int end = __ldg(&g_rowptr[node + 1]);
    float4 acc = make_float4(0.f, 0.f, 0.f, 0.f);
    for (; e + 1 < end; e += 2) {
        int s0 = __ldg(&g_csrc[e]);
        int s1 = __ldg(&g_csrc[e + 1]);
        float n0 = __ldg(&g_norm_out[s0]);
        float n1 = __ldg(&g_norm_out[s1]);
        float4 v0 = *((const float4*)(h + (size_t)s0 * Hh) + lane);
        float4 v1 = *((const float4*)(h + (size_t)s1 * Hh) + lane);
        acc.x += v0.x * n0 + v1.x * n1;
        acc.y += v0.y * n0 + v1.y * n1;
        acc.z += v0.z * n0 + v1.z * n1;
        acc.w += v0.w * n0 + v1.w * n1;
    }
    if (e < end) {
        int s0 = __ldg(&g_csrc[e]);
        float n0 = __ldg(&g_norm_out[s0]);
        float4 v0 = *((const float4*)(h + (size_t)s0 * Hh) + lane);
        acc.x += v0.x * n0;
        acc.y += v0.y * n0;
        acc.z += v0.z * n0;
        acc.w += v0.w * n0;
    }
    float ni = __ldg(&g_norm_in[node]);
    acc.x *= ni; acc.y *= ni; acc.z *= ni; acc.w *= ni;
    *((float4*)(agg + (size_t)node * Hh) + lane) = acc;
}

// ---------------- fused GEMM: out = relu(A @ W + b) ------------------------
// M-tile 128, N = K = 128 fixed. 256 threads, each an 8x8 microtile.
__global__ void gemm_bias_relu_kernel(const float* __restrict__ A,
                                      const float* __restrict__ W,
                                      const float* __restrict__ b,
                                      float* __restrict__ out, int M) {
    __shared__ float As[128][33];
    __shared__ float Ws[32][132];

    int tid = threadIdx.x;       // 0..255
    int tx = tid & 15;           // col group
    int ty = tid >> 4;           // row group
    int row0 = blockIdx.x * 128;

    float acc[8][8];
#pragma unroll
    for (int i = 0; i < 8; i++)
#pragma unroll
        for (int j = 0; j < 8; j++) acc[i][j] = 0.f;

    for (int kc = 0; kc < 128; kc += 32) {
        // load A chunk (128 rows x 32 cols)
#pragma unroll
        for (int p = 0; p < 4; ++p) {
            int r = (tid >> 3) + p * 32;
            int c = (tid & 7) * 4;
            int gr = row0 + r;
            float4 v = make_float4(0.f, 0.f, 0.f, 0.f);
            if (gr < M) {
                v = *(const float4*)(A + (size_t)gr * 128 + kc + c);
            }
            As[r][c + 0] = v.x;
            As[r][c + 1] = v.y;
            As[r][c + 2] = v.z;
            As[r][c + 3] = v.w;
        }
        // load W chunk (32 rows x 128 cols)
#pragma unroll
        for (int p = 0; p < 4; ++p) {
            int idx = tid + p * 256;      // float4 units, 1024 total
            int r = idx >> 5;             // 32 float4 per row
            int c = (idx & 31) * 4;
            float4 v = *(const float4*)(W + (size_t)(kc + r) * 128 + c);
            Ws[r][c + 0] = v.x;
            Ws[r][c + 1] = v.y;
            Ws[r][c + 2] = v.z;
            Ws[r][c + 3] = v.w;
        }
        __syncthreads();

#pragma unroll
        for (int k = 0; k < 32; ++k) {
            float a[8], w[8];
#pragma unroll
            for (int i = 0; i < 8; i++) a[i] = As[ty * 8 + i][k];
#pragma unroll
            for (int j = 0; j < 8; j++) w[j] = Ws[k][tx * 8 + j];
#pragma unroll
            for (int i = 0; i < 8; i++)
#pragma unroll
                for (int j = 0; j < 8; j++) acc[i][j] += a[i] * w[j];
        }
        __syncthreads();
    }

    // epilogue: bias + relu
#pragma unroll
    for (int i = 0; i < 8; i++) {
        int gr = row0 + ty * 8 + i;
        if (gr >= M) break;
#pragma unroll
        for (int j = 0; j < 8; j++) {
            int c = tx * 8 + j;
            float v = acc[i][j] + b[c];
            out[(size_t)gr * 128 + c] = fmaxf(v, 0.f);
        }
    }
}

// ---------------- readout: g[node2graph[n]] += h[n] ------------------------
__global__ void readout_kernel(const float* __restrict__ h,
                               const int* __restrict__ n2g) {
    int warp = (blockIdx.x * blockDim.x + threadIdx.x) >> 5;
    int lane = threadIdx.x & 31;
    if (warp >= Nn) return;
    int g = n2g[warp];
    float4 v = *((const float4*)(h + (size_t)warp * Hh) + lane);
    atomicAdd((float4*)(g_gsum + (size_t)g * Hh) + lane, v);
}

// ---------------- MLP head: relu(g@Wm1+bm1) @ Wm2 + bm2 --------------------
__global__ void mlp_kernel(const float* __restrict__ Wm1, const float* __restrict__ bm1,
                           const float* __restrict__ Wm2, const float* __restrict__ bm2,
                           float* __restrict__ out) {
    int gid = blockIdx.x;        // 0..G-1
    int j = threadIdx.x;         // 0..127
    const float* grow = g_gsum + (size_t)gid * Hh;
    float acc = bm1[j];
#pragma unroll 8
    for (int k = 0; k < Hh; k++) acc += grow[k] * Wm1[(size_t)k * Hh + j];
    acc = fmaxf(acc, 0.f);

    __shared__ float sm[Hh];
    sm[j] = acc * Wm2[j];        // Wm2 is [H,1]
    __syncthreads();
    for (int s = 64; s > 0; s >>= 1) {
        if (j < s) sm[j] += sm[j + s];
        __syncthreads();
    }
    if (j == 0) out[gid] = sm[0] + bm2[0];
}

// ---------------- launch ----------------------------------------------------
extern "C" void kernel_launch(void* const* d_in, const int* in_sizes, int n_in,
                              void* d_out, int out_size) {
    const float* x   = (const float*)d_in[0];
    const int* src   = (const int*)d_in[1];
    const int* dst   = (const int*)d_in[2];
    const int* n2g   = (const int*)d_in[3];
    const float* W0  = (const float*)d_in[4];
    const float* b0  = (const float*)d_in[5];
    const float* W1  = (const float*)d_in[6];
    const float* b1  = (const float*)d_in[7];
    const float* W2  = (const float*)d_in[8];
    const float* b2  = (const float*)d_in[9];
    const float* Wm1 = (const float*)d_in[10];
    const float* bm1 = (const float*)d_in[11];
    const float* Wm2 = (const float*)d_in[12];
    const float* bm2 = (const float*)d_in[13];
    float* out = (float*)d_out;

    void *p_h0, *p_h1, *p_agg;
    cudaGetSymbolAddress(&p_h0, g_h0);
    cudaGetSymbolAddress(&p_h1, g_h1);
    cudaGetSymbolAddress(&p_agg, g_agg);
    float* h0  = (float*)p_h0;
    float* h1  = (float*)p_h1;
    float* agg = (float*)p_agg;

    const int GEMM_BLOCKS   = (Nn + 127) / 128;
    const int GATHER_BLOCKS = (Nn + 7) / 8;        // 8 warps/block
    const int RD_BLOCKS     = (Nn + 7) / 8;

    // ---- CSR build + norms (once per launch) ----
    zero_cnt_kernel<<<(Nn + 255) / 256, 256>>>();
    hist_kernel<<<(Ee + 255) / 256, 256>>>(src, dst);
    norm_kernel<<<(Nn + 255) / 256, 256>>>();
    scan1_kernel<<<NBLK_SCAN, 256>>>();
    scan2_kernel<<<1, 128>>>(NBLK_SCAN);
    scan3_kernel<<<(Nn + 255) / 256, 256>>>();
    permute_kernel<<<(Ee + 255) / 256, 256>>>(src, dst);

    // ---- layer 1: x -> h0 ----
    gather_kernel<<<GATHER_BLOCKS, 256>>>(x, agg);
    gemm_bias_relu_kernel<<<GEMM_BLOCKS, 256>>>(agg, W0, b0, h0, Nn);

    // ---- layer 2: h0 -> h1 ----
    gather_kernel<<<GATHER_BLOCKS, 256>>>(h0, agg);
    gemm_bias_relu_kernel<<<GEMM_BLOCKS, 256>>>(agg, W1, b1, h1, Nn);

    // ---- layer 3: h1 -> h0 ----
    gather_kernel<<<GATHER_BLOCKS, 256>>>(h1, agg);
    gemm_bias_relu_kernel<<<GEMM_BLOCKS, 256>>>(agg, W2, b2, h0, Nn);

    // ---- readout + MLP head ----
    zero_g_kernel<<<(Gg * Hh + 255) / 256, 256>>>();
    readout_kernel<<<RD_BLOCKS, 256>>>(h0, n2g);
    mlp_kernel<<<Gg, Hh>>>(Wm1, bm1, Wm2, bm2, out);
}

// round 8
// speedup vs baseline: 2.2864x; 1.0301x over previous
#include <cuda_runtime.h>
#include <cuda_bf16.h>
#include <math.h>

#define Nn 100000
#define Ee 1600000
#define Gg 512
#define Hh 128
#define SCAN_CHUNK 1024
#define NBLK_SCAN ((Nn + SCAN_CHUNK - 1) / SCAN_CHUNK)   // 98

#define AP 132                       // As row pitch (floats)
#define FUSED_SMEM ((128 * AP + 32 * AP) * 4)   // 84480 bytes

// ---------------- scratch (device globals; no allocation allowed) ----------
__device__ float g_h0[(size_t)Nn * Hh];
__device__ float g_h1[(size_t)Nn * Hh];
__device__ float g_norm_out[Nn];
__device__ float g_norm_in[Nn];
__device__ float g_gsum[(size_t)Gg * Hh];

__device__ int g_cnt_in[Nn];
__device__ int g_cnt_out[Nn];
__device__ int g_rowptr[Nn + 1];
__device__ int g_cursor[Nn];
__device__ int g_csrc[Ee];
__device__ int g_partials[256];

// ---------------- zero kernels ---------------------------------------------
__global__ void zero_cnt_kernel() {
    int i = blockIdx.x * blockDim.x + threadIdx.x;
    if (i < Nn) { g_cnt_in[i] = 0; g_cnt_out[i] = 0; }
}

__global__ void zero_g_kernel() {
    int i = blockIdx.x * blockDim.x + threadIdx.x;
    if (i < Gg * Hh) g_gsum[i] = 0.f;
}

// ---------------- histogram (also yields degrees) --------------------------
__global__ void hist_kernel(const int* __restrict__ src, const int* __restrict__ dst) {
    int e = blockIdx.x * blockDim.x + threadIdx.x;
    if (e < Ee) {
        atomicAdd(&g_cnt_in[dst[e]], 1);
        atomicAdd(&g_cnt_out[src[e]], 1);
    }
}

__global__ void norm_kernel() {
    int i = blockIdx.x * blockDim.x + threadIdx.x;
    if (i < Nn) {
        g_norm_out[i] = rsqrtf(fmaxf((float)g_cnt_out[i], 1.f));
        g_norm_in[i]  = rsqrtf(fmaxf((float)g_cnt_in[i], 1.f));
    }
}

// ---------------- 3-phase exclusive scan of g_cnt_in -> g_rowptr -----------
__global__ void scan1_kernel() {
    __shared__ int sm[256];
    int b = blockIdx.x, t = threadIdx.x;
    int base = b * SCAN_CHUNK + t * 4;
    int v[4]; int s = 0;
#pragma unroll
    for (int i = 0; i < 4; i++) {
        int idx = base + i;
        v[i] = (idx < Nn) ? g_cnt_in[idx] : 0;
        s += v[i];
    }
    sm[t] = s;
    __syncthreads();
    for (int off = 1; off < 256; off <<= 1) {
        int x = (t >= off) ? sm[t - off] : 0;
        __syncthreads();
        if (t >= off) sm[t] += x;
        __syncthreads();
    }
    int run = (t > 0) ? sm[t - 1] : 0;
#pragma unroll
    for (int i = 0; i < 4; i++) {
        int idx = base + i;
        if (idx < Nn) g_rowptr[idx] = run;
        run += v[i];
    }
    if (t == 255) g_partials[b] = sm[255];
}

__global__ void scan2_kernel(int P) {
    __shared__ int sm[128];
    int t = threadIdx.x;
    sm[t] = (t < P) ? g_partials[t] : 0;
    __syncthreads();
    for (int off = 1; off < 128; off <<= 1) {
        int x = (t >= off) ? sm[t - off] : 0;
        __syncthreads();
        if (t >= off) sm[t] += x;
        __syncthreads();
    }
    if (t < P) g_partials[t] = (t > 0) ? sm[t - 1] : 0;
    if (t == P - 1) g_rowptr[Nn] = sm[P - 1];
}

__global__ void scan3_kernel() {
    int i = blockIdx.x * blockDim.x + threadIdx.x;
    if (i < Nn) {
        int v = g_rowptr[i] + g_partials[i / SCAN_CHUNK];
        g_rowptr[i] = v;
        g_cursor[i] = v;
    }
}

// ---------------- permute edges into CSR-by-dst ----------------------------
__global__ void permute_kernel(const int* __restrict__ src, const int* __restrict__ dst) {
    int e = blockIdx.x * blockDim.x + threadIdx.x;
    if (e < Ee) {
        int pos = atomicAdd(&g_cursor[dst[e]], 1);
        g_csrc[pos] = src[e];
    }
}

// ---------------- fused gather + GEMM + bias + relu ------------------------
// Per block: 128 node-rows. Phase 1: gather CSR neighbors of each row into
// smem A-tile (full K=128), scaled by norm_out[src] and norm_in[node].
// Phase 2: out = relu(A @ W + b), W staged in 32-wide k-chunks.
__global__ void gcn_fused_kernel(const float* __restrict__ h,
                                 const float* __restrict__ W,
                                 const float* __restrict__ b,
                                 float* __restrict__ out, int M) {
    extern __shared__ float smem[];
    float* As = smem;                 // [128][AP]
    float* Ws = smem + 128 * AP;      // [32][AP]

    int tid = threadIdx.x;            // 0..255
    int warp = tid >> 5;
    int lane = tid & 31;
    int row0 = blockIdx.x * 128;

    // ---- phase 1: gather A tile ----
#pragma unroll 1
    for (int rr = 0; rr < 16; ++rr) {
        int r = warp * 16 + rr;
        int node = row0 + r;
        float4 acc = make_float4(0.f, 0.f, 0.f, 0.f);
        if (node < M) {
            int e = __ldg(&g_rowptr[node]);
            int end = __ldg(&g_rowptr[node + 1]);
            for (; e + 1 < end; e += 2) {
                int s0 = __ldg(&g_csrc[e]);
                int s1 = __ldg(&g_csrc[e + 1]);
                float n0 = __ldg(&g_norm_out[s0]);
                float n1 = __ldg(&g_norm_out[s1]);
                float4 v0 = *((const float4*)(h + (size_t)s0 * Hh) + lane);
                float4 v1 = *((const float4*)(h + (size_t)s1 * Hh) + lane);
                acc.x += v0.x * n0 + v1.x * n1;
                acc.y += v0.y * n0 + v1.y * n1;
                acc.z += v0.z * n0 + v1.z * n1;
                acc.w += v0.w * n0 + v1.w * n1;
            }
            if (e < end) {
                int s0 = __ldg(&g_csrc[e]);
                float n0 = __ldg(&g_norm_out[s0]);
                float4 v0 = *((const float4*)(h + (size_t)s0 * Hh) + lane);
                acc.x += v0.x * n0;
                acc.y += v0.y * n0;
                acc.z += v0.z * n0;
                acc.w += v0.w * n0;
            }
            float ni = __ldg(&g_norm_in[node]);
            acc.x *= ni; acc.y *= ni; acc.z *= ni; acc.w *= ni;
        }
        float* d = As + r * AP + lane * 4;
        d[0] = acc.x; d[1] = acc.y; d[2] = acc.z; d[3] = acc.w;
    }
    __syncthreads();

    // ---- phase 2: GEMM from resident A tile ----
    int tx = tid & 15;           // col group
    int ty = tid >> 4;           // row group

    float acc[8][8];
#pragma unroll
    for (int i = 0; i < 8; i++)
#pragma unroll
        for (int j = 0; j < 8; j++) acc[i][j] = 0.f;

    for (int kc = 0; kc < 128; kc += 32) {
        // load W chunk (32 rows x 128 cols)
#pragma unroll
        for (int p = 0; p < 4; ++p) {
            int idx = tid + p * 256;      // float4 units, 1024 total
            int r = idx >> 5;             // 32 float4 per row
            int c = (idx & 31) * 4;
            float4 v = *(const float4*)(W + (size_t)(kc + r) * 128 + c);
            float* w = Ws + r * AP + c;
            w[0] = v.x; w[1] = v.y; w[2] = v.z; w[3] = v.w;
        }
        __syncthreads();

#pragma unroll
        for (int k = 0; k < 32; ++k) {
            float a[8], w[8];
#pragma unroll
            for (int i = 0; i < 8; i++) a[i] = As[(ty * 8 + i) * AP + kc + k];
#pragma unroll
            for (int j = 0; j < 8; j++) w[j] = Ws[k * AP + tx * 8 + j];
#pragma unroll
            for (int i = 0; i < 8; i++)
#pragma unroll
                for (int j = 0; j < 8; j++) acc[i][j] += a[i] * w[j];
        }
        __syncthreads();
    }

    // epilogue: bias + relu
#pragma unroll
    for (int i = 0; i < 8; i++) {
        int gr = row0 + ty * 8 + i;
        if (gr >= M) break;
#pragma unroll
        for (int j = 0; j < 8; j++) {
            int c = tx * 8 + j;
            float v = acc[i][j] + b[c];
            out[(size_t)gr * 128 + c] = fmaxf(v, 0.f);
        }
    }
}

// ---------------- readout: g[node2graph[n]] += h[n] ------------------------
__global__ void readout_kernel(const float* __restrict__ h,
                               const int* __restrict__ n2g) {
    int warp = (blockIdx.x * blockDim.x + threadIdx.x) >> 5;
    int lane = threadIdx.x & 31;
    if (warp >= Nn) return;
    int g = n2g[warp];
    float4 v = *((const float4*)(h + (size_t)warp * Hh) + lane);
    atomicAdd((float4*)(g_gsum + (size_t)g * Hh) + lane, v);
}

// ---------------- MLP head: relu(g@Wm1+bm1) @ Wm2 + bm2 --------------------
__global__ void mlp_kernel(const float* __restrict__ Wm1, const float* __restrict__ bm1,
                           const float* __restrict__ Wm2, const float* __restrict__ bm2,
                           float* __restrict__ out) {
    int gid = blockIdx.x;        // 0..G-1
    int j = threadIdx.x;         // 0..127
    const float* grow = g_gsum + (size_t)gid * Hh;
    float acc = bm1[j];
#pragma unroll 8
    for (int k = 0; k < Hh; k++) acc += grow[k] * Wm1[(size_t)k * Hh + j];
    acc = fmaxf(acc, 0.f);

    __shared__ float sm[Hh];
    sm[j] = acc * Wm2[j];        // Wm2 is [H,1]
    __syncthreads();
    for (int s = 64; s > 0; s >>= 1) {
        if (j < s) sm[j] += sm[j + s];
        __syncthreads();
    }
    if (j == 0) out[gid] = sm[0] + bm2[0];
}

// ---------------- launch ----------------------------------------------------
extern "C" void kernel_launch(void* const* d_in, const int* in_sizes, int n_in,
                              void* d_out, int out_size) {
    const float* x   = (const float*)d_in[0];
    const int* src   = (const int*)d_in[1];
    const int* dst   = (const int*)d_in[2];
    const int* n2g   = (const int*)d_in[3];
    const float* W0  = (const float*)d_in[4];
    const float* b0  = (const float*)d_in[5];
    const float* W1  = (const float*)d_in[6];
    const float* b1  = (const float*)d_in[7];
    const float* W2  = (const float*)d_in[8];
    const float* b2  = (const float*)d_in[9];
    const float* Wm1 = (const float*)d_in[10];
    const float* bm1 = (const float*)d_in[11];
    const float* Wm2 = (const float*)d_in[12];
    const float* bm2 = (const float*)d_in[13];
    float* out = (float*)d_out;

    void *p_h0, *p_h1;
    cudaGetSymbolAddress(&p_h0, g_h0);
    cudaGetSymbolAddress(&p_h1, g_h1);
    float* h0  = (float*)p_h0;
    float* h1  = (float*)p_h1;

    static int smem_set = 0;
    if (!smem_set) {
        cudaFuncSetAttribute(gcn_fused_kernel,
                             cudaFuncAttributeMaxDynamicSharedMemorySize,
                             FUSED_SMEM);
        smem_set = 1;
    }

    const int GEMM_BLOCKS = (Nn + 127) / 128;
    const int RD_BLOCKS   = (Nn + 7) / 8;

    // ---- CSR build + norms (once per launch) ----
    zero_cnt_kernel<<<(Nn + 255) / 256, 256>>>();
    hist_kernel<<<(Ee + 255) / 256, 256>>>(src, dst);
    norm_kernel<<<(Nn + 255) / 256, 256>>>();
    scan1_kernel<<<NBLK_SCAN, 256>>>();
    scan2_kernel<<<1, 128>>>(NBLK_SCAN);
    scan3_kernel<<<(Nn + 255) / 256, 256>>>();
    permute_kernel<<<(Ee + 255) / 256, 256>>>(src, dst);

    // ---- 3 fused GCN layers ----
    gcn_fused_kernel<<<GEMM_BLOCKS, 256, FUSED_SMEM>>>(x,  W0, b0, h0, Nn);
    gcn_fused_kernel<<<GEMM_BLOCKS, 256, FUSED_SMEM>>>(h0, W1, b1, h1, Nn);
    gcn_fused_kernel<<<GEMM_BLOCKS, 256, FUSED_SMEM>>>(h1, W2, b2, h0, Nn);

    // ---- readout + MLP head ----
    zero_g_kernel<<<(Gg * Hh + 255) / 256, 256>>>();
    readout_kernel<<<RD_BLOCKS, 256>>>(h0, n2g);
    mlp_kernel<<<Gg, Hh>>>(Wm1, bm1, Wm2, bm2, out);
}

// round 11
// speedup vs baseline: 2.7734x; 1.2130x over previous
#include <cuda_runtime.h>
#include <cuda_bf16.h>
#include <math.h>

#define Nn 100000
#define Ee 1600000
#define Gg 512
#define Hh 128
#define SCAN_CHUNK 1024
#define NBLK_SCAN ((Nn + SCAN_CHUNK - 1) / SCAN_CHUNK)   // 98

#define AP 132                                  // A-chunk row pitch (floats)
#define SMEM_W_FLOATS (128 * 128)               // W: flat 128x128
#define SMEM_A_FLOATS (2 * 32 * AP)             // double-buffered 32-row chunks
#define FUSED_SMEM ((SMEM_W_FLOATS + SMEM_A_FLOATS) * 4)   // 99328 bytes

#define BAR_FULL0 1
#define BAR_FULL1 2
#define BAR_FREE0 3
#define BAR_FREE1 4
#define BAR_CONS  5

__device__ __forceinline__ void bar_sync(int id, int cnt) {
    asm volatile("bar.sync %0, %1;" :: "r"(id), "r"(cnt) : "memory");
}
__device__ __forceinline__ void bar_arrive(int id, int cnt) {
    asm volatile("bar.arrive %0, %1;" :: "r"(id), "r"(cnt) : "memory");
}

// ---------------- scratch (device globals; no allocation allowed) ----------
__device__ float g_h0[(size_t)Nn * Hh];
__device__ float g_h1[(size_t)Nn * Hh];
__device__ float g_norm_out[Nn];
__device__ float g_norm_in[Nn];
__device__ float g_gsum[(size_t)Gg * Hh];

__device__ int g_cnt_in[Nn];
__device__ int g_cnt_out[Nn];
__device__ int g_rowptr[Nn + 1];
__device__ int g_cursor[Nn];
__device__ int g_csrc[Ee];
__device__ int g_partials[256];

// ---------------- zero kernels ---------------------------------------------
__global__ void zero_cnt_kernel() {
    int i = blockIdx.x * blockDim.x + threadIdx.x;
    if (i < Nn) { g_cnt_in[i] = 0; g_cnt_out[i] = 0; }
}

__global__ void zero_g_kernel() {
    int i = blockIdx.x * blockDim.x + threadIdx.x;
    if (i < Gg * Hh) g_gsum[i] = 0.f;
}

// ---------------- histogram (also yields degrees) --------------------------
__global__ void hist_kernel(const int* __restrict__ src, const int* __restrict__ dst) {
    int e = blockIdx.x * blockDim.x + threadIdx.x;
    if (e < Ee) {
        atomicAdd(&g_cnt_in[dst[e]], 1);
        atomicAdd(&g_cnt_out[src[e]], 1);
    }
}

__global__ void norm_kernel() {
    int i = blockIdx.x * blockDim.x + threadIdx.x;
    if (i < Nn) {
        g_norm_out[i] = rsqrtf(fmaxf((float)g_cnt_out[i], 1.f));
        g_norm_in[i]  = rsqrtf(fmaxf((float)g_cnt_in[i], 1.f));
    }
}

// ---------------- 3-phase exclusive scan of g_cnt_in -> g_rowptr -----------
__global__ void scan1_kernel() {
    __shared__ int sm[256];
    int b = blockIdx.x, t = threadIdx.x;
    int base = b * SCAN_CHUNK + t * 4;
    int v[4]; int s = 0;
#pragma unroll
    for (int i = 0; i < 4; i++) {
        int idx = base + i;
        v[i] = (idx < Nn) ? g_cnt_in[idx] : 0;
        s += v[i];
    }
    sm[t] = s;
    __syncthreads();
    for (int off = 1; off < 256; off <<= 1) {
        int x = (t >= off) ? sm[t - off] : 0;
        __syncthreads();
        if (t >= off) sm[t] += x;
        __syncthreads();
    }
    int run = (t > 0) ? sm[t - 1] : 0;
#pragma unroll
    for (int i = 0; i < 4; i++) {
        int idx = base + i;
        if (idx < Nn) g_rowptr[idx] = run;
        run += v[i];
    }
    if (t == 255) g_partials[b] = sm[255];
}

__global__ void scan2_kernel(int P) {
    __shared__ int sm[128];
    int t = threadIdx.x;
    sm[t] = (t < P) ? g_partials[t] : 0;
    __syncthreads();
    for (int off = 1; off < 128; off <<= 1) {
        int x = (t >= off) ? sm[t - off] : 0;
        __syncthreads();
        if (t >= off) sm[t] += x;
        __syncthreads();
    }
    if (t < P) g_partials[t] = (t > 0) ? sm[t - 1] : 0;
    if (t == P - 1) g_rowptr[Nn] = sm[P - 1];
}

__global__ void scan3_kernel() {
    int i = blockIdx.x * blockDim.x + threadIdx.x;
    if (i < Nn) {
        int v = g_rowptr[i] + g_partials[i / SCAN_CHUNK];
        g_rowptr[i] = v;
        g_cursor[i] = v;
    }
}

// ---------------- permute edges into CSR-by-dst ----------------------------
__global__ void permute_kernel(const int* __restrict__ src, const int* __restrict__ dst) {
    int e = blockIdx.x * blockDim.x + threadIdx.x;
    if (e < Ee) {
        int pos = atomicAdd(&g_cursor[dst[e]], 1);
        g_csrc[pos] = src[e];
    }
}

// ---------------- warp-specialized fused layer ------------------------------
// 384 threads: warps 0-7 = producers (CSR gather of 32-row A chunks, double
// buffered), warps 8-11 = consumers (32x128x128 GEMM per chunk + bias + relu).
// W held fully in smem. Named-barrier producer/consumer pipeline.
__global__ __launch_bounds__(384, 2)
void gcn_ws_kernel(const float* __restrict__ h,
                   const float* __restrict__ W,
                   const float* __restrict__ bias,
                   float* __restrict__ out, int M) {
    extern __shared__ float smem[];
    float* Ws = smem;                       // [128][128] flat
    float* As = smem + SMEM_W_FLOATS;       // 2 x [32][AP]

    int tid = threadIdx.x;
    int row0 = blockIdx.x * 128;

    if (tid < 256) {
        // ================= producers =================
        int w = tid >> 5;                   // 0..7
        int lane = tid & 31;
#pragma unroll 1
        for (int c0 = 0; c0 < 4; ++c0) {
            int bsel = c0 & 1;
            if (c0 >= 2) bar_sync(BAR_FREE0 + bsel, 384);
            float* Ab = As + bsel * 32 * AP;
#pragma unroll 1
            for (int q = 0; q < 4; ++q) {
                int row_local = w + 8 * q;              // 0..31
                int node = row0 + c0 * 32 + row_local;
                float4 acc = make_float4(0.f, 0.f, 0.f, 0.f);
                if (node < M) {
                    int e = __ldg(&g_rowptr[node]);
                    int end = __ldg(&g_rowptr[node + 1]);
                    for (; e + 1 < end; e += 2) {
                        int s0 = __ldg(&g_csrc[e]);
                        int s1 = __ldg(&g_csrc[e + 1]);
                        float n0 = __ldg(&g_norm_out[s0]);
                        float n1 = __ldg(&g_norm_out[s1]);
                        float4 v0 = *((const float4*)(h + (size_t)s0 * Hh) + lane);
                        float4 v1 = *((const float4*)(h + (size_t)s1 * Hh) + lane);
                        acc.x += v0.x * n0 + v1.x * n1;
                        acc.y += v0.y * n0 + v1.y * n1;
                        acc.z += v0.z * n0 + v1.z * n1;
                        acc.w += v0.w * n0 + v1.w * n1;
                    }
                    if (e < end) {
                        int s0 = __ldg(&g_csrc[e]);
                        float n0 = __ldg(&g_norm_out[s0]);
                        float4 v0 = *((const float4*)(h + (size_t)s0 * Hh) + lane);
                        acc.x += v0.x * n0;
                        acc.y += v0.y * n0;
                        acc.z += v0.z * n0;
                        acc.w += v0.w * n0;
                    }
                    float ni = __ldg(&g_norm_in[node]);
                    acc.x *= ni; acc.y *= ni; acc.z *= ni; acc.w *= ni;
                }
                float* d = Ab + row_local * AP + lane * 4;
                d[0] = acc.x; d[1] = acc.y; d[2] = acc.z; d[3] = acc.w;
            }
            bar_arrive(BAR_FULL0 + bsel, 384);
        }
    } else {
        // ================= consumers =================
        int ctid = tid - 256;               // 0..127
        int r = ctid >> 5;                  // row group 0..3 (8 rows each)
        int cc = ctid & 31;                 // col group (4 cols)

        // stage W (flat copy), overlapped with producers' first gather
        {
            const float4* Wv = (const float4*)W;
            float4* Wsv = (float4*)Ws;
#pragma unroll
            for (int i = 0; i < 32; ++i)
                Wsv[ctid + i * 128] = Wv[ctid + i * 128];
        }
        float4 bv = ((const float4*)bias)[cc];
        bar_sync(BAR_CONS, 128);

#pragma unroll 1
        for (int c0 = 0; c0 < 4; ++c0) {
            int bsel = c0 & 1;
            bar_sync(BAR_FULL0 + bsel, 384);
            const float* Ab = As + bsel * 32 * AP;

            float acc[8][4];
#pragma unroll
            for (int i = 0; i < 8; i++)
#pragma unroll
                for (int j = 0; j < 4; j++) acc[i][j] = 0.f;

#pragma unroll 4
            for (int k = 0; k < 128; ++k) {
                float4 wv = *(const float4*)(Ws + k * 128 + cc * 4);
#pragma unroll
                for (int i = 0; i < 8; i++) {
                    float a = Ab[(r * 8 + i) * AP + k];   // broadcast load
                    acc[i][0] += a * wv.x;
                    acc[i][1] += a * wv.y;
                    acc[i][2] += a * wv.z;
                    acc[i][3] += a * wv.w;
                }
            }

            if (c0 < 2) bar_arrive(BAR_FREE0 + bsel, 384);

            // epilogue: bias + relu + store
#pragma unroll
            for (int i = 0; i < 8; i++) {
                int gr = row0 + c0 * 32 + r * 8 + i;
                if (gr < M) {
                    float4 o;
                    o.x = fmaxf(acc[i][0] + bv.x, 0.f);
                    o.y = fmaxf(acc[i][1] + bv.y, 0.f);
                    o.z = fmaxf(acc[i][2] + bv.z, 0.f);
                    o.w = fmaxf(acc[i][3] + bv.w, 0.f);
                    *(float4*)(out + (size_t)gr * 128 + cc * 4) = o;
                }
            }
        }
    }
}

// ---------------- readout: g[node2graph[n]] += h[n] ------------------------
__global__ void readout_kernel(const float* __restrict__ h,
                               const int* __restrict__ n2g) {
    int warp = (blockIdx.x * blockDim.x + threadIdx.x) >> 5;
    int lane = threadIdx.x & 31;
    if (warp >= Nn) return;
    int g = n2g[warp];
    float4 v = *((const float4*)(h + (size_t)warp * Hh) + lane);
    atomicAdd((float4*)(g_gsum + (size_t)g * Hh) + lane, v);
}

// ---------------- MLP head: relu(g@Wm1+bm1) @ Wm2 + bm2 --------------------
__global__ void mlp_kernel(const float* __restrict__ Wm1, const float* __restrict__ bm1,
                           const float* __restrict__ Wm2, const float* __restrict__ bm2,
                           float* __restrict__ out) {
    int gid = blockIdx.x;        // 0..G-1
    int j = threadIdx.x;         // 0..127
    const float* grow = g_gsum + (size_t)gid * Hh;
    float acc = bm1[j];
#pragma unroll 8
    for (int k = 0; k < Hh; k++) acc += grow[k] * Wm1[(size_t)k * Hh + j];
    acc = fmaxf(acc, 0.f);

    __shared__ float sm[Hh];
    sm[j] = acc * Wm2[j];        // Wm2 is [H,1]
    __syncthreads();
    for (int s = 64; s > 0; s >>= 1) {
        if (j < s) sm[j] += sm[j + s];
        __syncthreads();
    }
    if (j == 0) out[gid] = sm[0] + bm2[0];
}

// ---------------- launch ----------------------------------------------------
extern "C" void kernel_launch(void* const* d_in, const int* in_sizes, int n_in,
                              void* d_out, int out_size) {
    const float* x   = (const float*)d_in[0];
    const int* src   = (const int*)d_in[1];
    const int* dst   = (const int*)d_in[2];
    const int* n2g   = (const int*)d_in[3];
    const float* W0  = (const float*)d_in[4];
    const float* b0  = (const float*)d_in[5];
    const float* W1  = (const float*)d_in[6];
    const float* b1  = (const float*)d_in[7];
    const float* W2  = (const float*)d_in[8];
    const float* b2  = (const float*)d_in[9];
    const float* Wm1 = (const float*)d_in[10];
    const float* bm1 = (const float*)d_in[11];
    const float* Wm2 = (const float*)d_in[12];
    const float* bm2 = (const float*)d_in[13];
    float* out = (float*)d_out;

    void *p_h0, *p_h1;
    cudaGetSymbolAddress(&p_h0, g_h0);
    cudaGetSymbolAddress(&p_h1, g_h1);
    float* h0  = (float*)p_h0;
    float* h1  = (float*)p_h1;

    static int smem_set = 0;
    if (!smem_set) {
        cudaFuncSetAttribute(gcn_ws_kernel,
                             cudaFuncAttributeMaxDynamicSharedMemorySize,
                             FUSED_SMEM);
        smem_set = 1;
    }

    const int LAYER_BLOCKS = (Nn + 127) / 128;   // 782
    const int RD_BLOCKS    = (Nn + 7) / 8;

    // ---- CSR build + norms (once per launch) ----
    zero_cnt_kernel<<<(Nn + 255) / 256, 256>>>();
    hist_kernel<<<(Ee + 255) / 256, 256>>>(src, dst);
    norm_kernel<<<(Nn + 255) / 256, 256>>>();
    scan1_kernel<<<NBLK_SCAN, 256>>>();
    scan2_kernel<<<1, 128>>>(NBLK_SCAN);
    scan3_kernel<<<(Nn + 255) / 256, 256>>>();
    permute_kernel<<<(Ee + 255) / 256, 256>>>(src, dst);

    // ---- 3 warp-specialized fused GCN layers ----
    gcn_ws_kernel<<<LAYER_BLOCKS, 384, FUSED_SMEM>>>(x,  W0, b0, h0, Nn);
    gcn_ws_kernel<<<LAYER_BLOCKS, 384, FUSED_SMEM>>>(h0, W1, b1, h1, Nn);
    gcn_ws_kernel<<<LAYER_BLOCKS, 384, FUSED_SMEM>>>(h1, W2, b2, h0, Nn);

    // ---- readout + MLP head ----
    zero_g_kernel<<<(Gg * Hh + 255) / 256, 256>>>();
    readout_kernel<<<RD_BLOCKS, 256>>>(h0, n2g);
    mlp_kernel<<<Gg, Hh>>>(Wm1, bm1, Wm2, bm2, out);
}